// round 1
// baseline (speedup 1.0000x reference)
#include <cuda_runtime.h>

// out = -weight * sum_{k=0}^{M-1} f[k]*f[k+D] / (N-1),  M = (N-1)*D
// Pure streaming fp32 reduction. Two read streams offset by D*4 = 8KB;
// second stream is expected to be L2-served, so DRAM traffic ~= 1x input.

#define RED_BLOCKS 1480
#define RED_THREADS 256

__device__ float g_partials[RED_BLOCKS];

__global__ __launch_bounds__(RED_THREADS)
void shifted_dot_kernel(const float4* __restrict__ in4, long long Mv, int Dv) {
    float acc = 0.0f;
    const long long stride = (long long)gridDim.x * blockDim.x;
    for (long long t = (long long)blockIdx.x * blockDim.x + threadIdx.x;
         t < Mv; t += stride) {
        float4 a = in4[t];
        float4 b = in4[t + Dv];
        acc += a.x * b.x + a.y * b.y + a.z * b.z + a.w * b.w;
    }
    // warp reduce
    #pragma unroll
    for (int o = 16; o > 0; o >>= 1)
        acc += __shfl_xor_sync(0xffffffff, acc, o);

    __shared__ float s[RED_THREADS / 32];
    if ((threadIdx.x & 31) == 0) s[threadIdx.x >> 5] = acc;
    __syncthreads();

    if (threadIdx.x < 32) {
        float v = (threadIdx.x < RED_THREADS / 32) ? s[threadIdx.x] : 0.0f;
        #pragma unroll
        for (int o = 4; o > 0; o >>= 1)
            v += __shfl_xor_sync(0xffffffff, v, o);
        if (threadIdx.x == 0) g_partials[blockIdx.x] = v;
    }
}

__global__ __launch_bounds__(1024)
void finalize_kernel(const float* __restrict__ weight, float* __restrict__ out,
                     int nblocks, float inv_nm1) {
    float acc = 0.0f;
    for (int i = threadIdx.x; i < nblocks; i += blockDim.x)
        acc += g_partials[i];
    #pragma unroll
    for (int o = 16; o > 0; o >>= 1)
        acc += __shfl_xor_sync(0xffffffff, acc, o);

    __shared__ float s[32];
    if ((threadIdx.x & 31) == 0) s[threadIdx.x >> 5] = acc;
    __syncthreads();

    if (threadIdx.x < 32) {
        float v = s[threadIdx.x];
        #pragma unroll
        for (int o = 16; o > 0; o >>= 1)
            v += __shfl_xor_sync(0xffffffff, v, o);
        if (threadIdx.x == 0)
            out[0] = -(*weight) * v * inv_nm1;
    }
}

extern "C" void kernel_launch(void* const* d_in, const int* in_sizes, int n_in,
                              void* d_out, int out_size) {
    const float* factor = (const float*)d_in[0];
    const float* weight = (const float*)d_in[1];
    float* out = (float*)d_out;

    const int D = 2000;
    const long long total = (long long)in_sizes[0];   // N * D
    const long long N = total / D;
    const long long M = (N - 1) * (long long)D;        // pair elements
    const long long Mv = M / 4;                        // float4 count (D % 4 == 0)
    const int Dv = D / 4;

    shifted_dot_kernel<<<RED_BLOCKS, RED_THREADS>>>(
        (const float4*)factor, Mv, Dv);
    finalize_kernel<<<1, 1024>>>(weight, out, RED_BLOCKS,
                                 1.0f / (float)(N - 1));
}

// round 2
// speedup vs baseline: 1.0469x; 1.0469x over previous
#include <cuda_runtime.h>

// out = -weight * sum_{k=0}^{M-1} f[k]*f[k+D] / (N-1),  M = (N-1)*D, D=2000.
//
// Each block owns a CONTIGUOUS segment and sweeps it sequentially, so the
// b-stream load at k+D warms L1 for the a-stream load of the same line 8KB
// later -> duplicate read served by L1, L2 traffic ~1x instead of 2x.
// Single kernel: threadfence last-block-done reduction (self-resetting
// counter -> graph-replay safe, deterministic order).

#define NBLOCKS 1520
#define NTHREADS 256

__device__ float g_partials[NBLOCKS];
__device__ unsigned int g_count = 0;

__global__ __launch_bounds__(NTHREADS)
void shifted_dot_fused(const float4* __restrict__ in4, long long Mv, int Dv,
                       const float* __restrict__ weight, float* __restrict__ out,
                       float inv_nm1) {
    const long long per = (Mv + gridDim.x - 1) / gridDim.x;
    const long long seg_beg = (long long)blockIdx.x * per;
    long long seg_end = seg_beg + per;
    if (seg_end > Mv) seg_end = Mv;

    float acc = 0.0f;
    long long t = seg_beg + threadIdx.x;

    // 4x unrolled: 8 outstanding 16B loads per thread per iteration.
    for (; t + 3 * NTHREADS < seg_end; t += 4 * NTHREADS) {
        float4 a0 = in4[t];
        float4 a1 = in4[t + NTHREADS];
        float4 a2 = in4[t + 2 * NTHREADS];
        float4 a3 = in4[t + 3 * NTHREADS];
        float4 b0 = in4[t + Dv];
        float4 b1 = in4[t + NTHREADS + Dv];
        float4 b2 = in4[t + 2 * NTHREADS + Dv];
        float4 b3 = in4[t + 3 * NTHREADS + Dv];
        acc += a0.x * b0.x + a0.y * b0.y + a0.z * b0.z + a0.w * b0.w;
        acc += a1.x * b1.x + a1.y * b1.y + a1.z * b1.z + a1.w * b1.w;
        acc += a2.x * b2.x + a2.y * b2.y + a2.z * b2.z + a2.w * b2.w;
        acc += a3.x * b3.x + a3.y * b3.y + a3.z * b3.z + a3.w * b3.w;
    }
    for (; t < seg_end; t += NTHREADS) {
        float4 a = in4[t];
        float4 b = in4[t + Dv];
        acc += a.x * b.x + a.y * b.y + a.z * b.z + a.w * b.w;
    }

    // block reduce
    #pragma unroll
    for (int o = 16; o > 0; o >>= 1)
        acc += __shfl_xor_sync(0xffffffff, acc, o);

    __shared__ float s[NTHREADS / 32];
    if ((threadIdx.x & 31) == 0) s[threadIdx.x >> 5] = acc;
    __syncthreads();

    __shared__ bool is_last;
    if (threadIdx.x == 0) {
        float v = 0.0f;
        #pragma unroll
        for (int i = 0; i < NTHREADS / 32; i++) v += s[i];
        g_partials[blockIdx.x] = v;
        __threadfence();
        unsigned int old = atomicAdd(&g_count, 1u);
        is_last = (old == gridDim.x - 1);
    }
    __syncthreads();

    if (is_last) {
        // final reduction over all block partials (fixed order -> deterministic)
        const volatile float* p = g_partials;
        float v = 0.0f;
        for (int i = threadIdx.x; i < (int)gridDim.x; i += NTHREADS)
            v += p[i];
        #pragma unroll
        for (int o = 16; o > 0; o >>= 1)
            v += __shfl_xor_sync(0xffffffff, v, o);

        __shared__ float s2[NTHREADS / 32];
        if ((threadIdx.x & 31) == 0) s2[threadIdx.x >> 5] = v;
        __syncthreads();
        if (threadIdx.x == 0) {
            float tot = 0.0f;
            #pragma unroll
            for (int i = 0; i < NTHREADS / 32; i++) tot += s2[i];
            out[0] = -(*weight) * tot * inv_nm1;
            g_count = 0;  // reset for next graph replay
        }
    }
}

extern "C" void kernel_launch(void* const* d_in, const int* in_sizes, int n_in,
                              void* d_out, int out_size) {
    const float* factor = (const float*)d_in[0];
    const float* weight = (const float*)d_in[1];
    float* out = (float*)d_out;

    const int D = 2000;
    const long long total = (long long)in_sizes[0];   // N * D
    const long long N = total / D;
    const long long M = (N - 1) * (long long)D;       // pair elements, divisible by 4
    const long long Mv = M / 4;                       // float4 count
    const int Dv = D / 4;

    shifted_dot_fused<<<NBLOCKS, NTHREADS>>>(
        (const float4*)factor, Mv, Dv, weight, out, 1.0f / (float)(N - 1));
}